// round 1
// baseline (speedup 1.0000x reference)
#include <cuda_runtime.h>

// GaussianBlur2D: separable 201-tap Gaussian, sigma=25, zero padding.
// Input  x: (64, 544, 960) fp32
// Output y: same shape (flattened (1,1,T,H,W))
// Pass 1 (hblur): blur along W, x -> g_tmp
// Pass 2 (vblur): blur along H, g_tmp -> out
// (Reference does H then W; separable conv commutes.)

#define Wd   960
#define Hd   544
#define Td   64
#define PAD  100
#define KSZ  201

__device__ float g_tmp[Td * Hd * Wd];

// ---------------- compile-time Gaussian weights (must fold to FFMA-imm) ------
__host__ __device__ constexpr double cexp(double x) {
    // x in [-8, 0]; exp(x) = 2^n * exp(r), |r| <= ~0.3466
    int n = (int)(x * 1.4426950408889634 - 0.5);   // round for x <= 0
    double r = x - (double)n * 0.69314718055994530941723212;
    double term = 1.0, p = 1.0;
    for (int k = 1; k <= 16; k++) { term *= r / (double)k; p += term; }
    double s = 1.0;
    for (int i = 0; i < -n; i++) s *= 0.5;
    return p * s;
}

struct GK { float v[KSZ]; };

__host__ __device__ constexpr GK make_gk() {
    GK g{};
    for (int i = 0; i < KSZ; i++) {
        double r = (double)(i - PAD);
        double e = cexp(-(r * r) / (2.0 * 25.0 * 25.0));
        g.v[i] = (float)(e / 62.665706865775006);   // sigma*sqrt(2*pi)
    }
    return g;
}

// ---------------- Pass 1: horizontal blur (along W) --------------------------
// Block: 256 threads = 32 rows (lane) x 8 warps. Out tile: 32 rows x 64 cols.
// Shared staged transposed (pitch 33): s[col][row], conv axis = col.
// Each thread: 8 consecutive out-cols, register sliding window over taps.
#define HT_C 64
#define HS_C (HT_C + 2 * PAD + 1)   // 265 (last col is unused pad)

__global__ void __launch_bounds__(256) hblur(const float* __restrict__ x) {
    __shared__ float s[HS_C * 33];
    const int tid  = threadIdx.x;
    const int lane = tid & 31;       // row within 32-row group
    const int wid  = tid >> 5;
    const int c0   = blockIdx.x * HT_C;   // out-col base
    const int row0 = blockIdx.y * 32;     // global row base (rows = T*H)

    // stage: 264 cols x 32 rows, coalesced over cols, conflict-free stores
    for (int idx = tid; idx < 32 * (HT_C + 2 * PAD); idx += 256) {
        int c = idx % (HT_C + 2 * PAD);
        int r = idx / (HT_C + 2 * PAD);
        int gc = c0 - PAD + c;
        float v = 0.0f;
        if (gc >= 0 && gc < Wd) v = x[(row0 + r) * Wd + gc];
        s[c * 33 + r] = v;
    }
    __syncthreads();

    constexpr GK gk = make_gk();
    const int cbase = wid * 8;

    float acc[8] = {0.f, 0.f, 0.f, 0.f, 0.f, 0.f, 0.f, 0.f};
    float w[8];
#pragma unroll
    for (int i = 0; i < 8; i++) w[i] = s[(cbase + i) * 33 + lane];

#pragma unroll
    for (int t = 0; t < KSZ; t++) {
#pragma unroll
        for (int i = 0; i < 8; i++) acc[i] += gk.v[t] * w[i];
#pragma unroll
        for (int i = 0; i < 7; i++) w[i] = w[i + 1];
        if (t < KSZ - 1) w[7] = s[(cbase + t + 8) * 33 + lane];
    }

    // transpose-stage outputs through shared for coalesced global stores
    __syncthreads();
#pragma unroll
    for (int i = 0; i < 8; i++) s[(cbase + i) * 33 + lane] = acc[i];
    __syncthreads();
    for (int idx = tid; idx < HT_C * 32; idx += 256) {
        int c = idx % HT_C;
        int r = idx / HT_C;
        g_tmp[(row0 + r) * Wd + c0 + c] = s[c * 33 + r];
    }
}

// ---------------- Pass 2: vertical blur (along H) ----------------------------
// Block: 256 threads = 32 cols (lane) x 8 warps. Out tile: 64 rows x 32 cols.
// Shared: s[row][col32], conv axis = row. All LDS lane-consecutive.
#define VT_R 64
#define VS_R (VT_R + 2 * PAD + 1)   // 265 (last row unused pad)

__global__ void __launch_bounds__(256) vblur(float* __restrict__ y) {
    __shared__ float s[VS_R * 32];
    const int tid  = threadIdx.x;
    const int lane = tid & 31;       // col within 32-col group
    const int wid  = tid >> 5;
    const int frame = blockIdx.z;
    const int r0 = blockIdx.y * VT_R;
    const int c0 = blockIdx.x * 32;
    const float* xf = g_tmp + frame * (Hd * Wd);

    for (int idx = tid; idx < (VT_R + 2 * PAD) * 32; idx += 256) {
        int c = idx & 31;
        int r = idx >> 5;
        int gr = r0 - PAD + r;
        float v = 0.0f;
        if (gr >= 0 && gr < Hd) v = xf[gr * Wd + c0 + c];
        s[r * 32 + c] = v;
    }
    __syncthreads();

    constexpr GK gk = make_gk();
    const int rbase = wid * 8;

    float acc[8] = {0.f, 0.f, 0.f, 0.f, 0.f, 0.f, 0.f, 0.f};
    float w[8];
#pragma unroll
    for (int i = 0; i < 8; i++) w[i] = s[(rbase + i) * 32 + lane];

#pragma unroll
    for (int t = 0; t < KSZ; t++) {
#pragma unroll
        for (int i = 0; i < 8; i++) acc[i] += gk.v[t] * w[i];
#pragma unroll
        for (int i = 0; i < 7; i++) w[i] = w[i + 1];
        if (t < KSZ - 1) w[7] = s[(rbase + t + 8) * 32 + lane];
    }

    float* yf = y + frame * (Hd * Wd);
#pragma unroll
    for (int i = 0; i < 8; i++) {
        int gr = r0 + rbase + i;
        if (gr < Hd) yf[gr * Wd + c0 + lane] = acc[i];   // coalesced: lanes -> cols
    }
}

// ---------------- launch -----------------------------------------------------
extern "C" void kernel_launch(void* const* d_in, const int* in_sizes, int n_in,
                              void* d_out, int out_size) {
    const float* x = (const float*)d_in[0];
    float* out = (float*)d_out;

    // Pass 1: rows = T*H = 34816 (divisible by 32), cols 960 = 15*64
    hblur<<<dim3(Wd / HT_C, (Td * Hd) / 32), 256>>>(x);
    // Pass 2: 30 col-tiles, ceil(544/64)=9 row-tiles, 64 frames
    vblur<<<dim3(Wd / 32, (Hd + VT_R - 1) / VT_R, Td), 256>>>(out);
}

// round 3
// speedup vs baseline: 1.1475x; 1.1475x over previous
#include <cuda_runtime.h>

// GaussianBlur2D: separable 201-tap Gaussian, sigma=25, zero padding.
// x: (64, 544, 960) fp32 -> same shape.
// Pass 1 (hblur): blur along W, x -> g_tmp     (tiles: 32 rows x 120 cols)
// Pass 2 (vblur): blur along H, g_tmp -> out   (tiles: 136 rows x 32 cols)
//
// Inner loop form: broadcast one shared value v = s[j] into NOUT accumulators
// with distinct compile-time-immediate weights k[j-i]:
//   per j:  1 LDS + NOUT FFMA-imm, zero MOVs  ->  fma issue fraction ~94%.

#define Wd   960
#define Hd   544
#define Td   64
#define PAD  100
#define KSZ  201

__device__ float g_tmp[Td * Hd * Wd];

// ---------------- compile-time Gaussian weights (fold to FFMA-imm) -----------
__host__ __device__ constexpr double cexp(double x) {
    int n = (int)(x * 1.4426950408889634 - 0.5);   // for x <= 0
    double r = x - (double)n * 0.69314718055994530941723212;
    double term = 1.0, p = 1.0;
    for (int k = 1; k <= 16; k++) { term *= r / (double)k; p += term; }
    double s = 1.0;
    for (int i = 0; i < -n; i++) s *= 0.5;
    return p * s;
}

struct GK { float v[KSZ]; };

__host__ __device__ constexpr GK make_gk() {
    GK g{};
    for (int i = 0; i < KSZ; i++) {
        double r = (double)(i - PAD);
        double e = cexp(-(r * r) / (2.0 * 25.0 * 25.0));
        g.v[i] = (float)(e / 62.665706865775006);   // sigma*sqrt(2*pi)
    }
    return g;
}

// ---------------- Pass 1: horizontal blur (along W) --------------------------
// Block: 256 threads = 32 rows (lane) x 8 warps; each warp 15 consecutive cols.
// Out tile: 32 rows x 120 cols. Shared transposed (pitch 33): s[col][row].
#define H_NOUT 15
#define HT_C   (8 * H_NOUT)          // 120
#define HS_C   (HT_C + 2 * PAD)      // 320 staged cols

__global__ void __launch_bounds__(256) hblur(const float* __restrict__ x) {
    __shared__ float s[HS_C * 33];
    const int tid  = threadIdx.x;
    const int lane = tid & 31;           // row within 32-row group
    const int wid  = tid >> 5;
    const int c0   = blockIdx.x * HT_C;  // out-col base
    const int row0 = blockIdx.y * 32;    // global row base (rows = T*H)

    // stage 320 cols x 32 rows: coalesced global reads, conflict-free STS
    for (int idx = tid; idx < 32 * HS_C; idx += 256) {
        int c = idx % HS_C;
        int r = idx / HS_C;
        int gc = c0 - PAD + c;
        float v = 0.0f;
        if (gc >= 0 && gc < Wd) v = x[(row0 + r) * Wd + gc];
        s[c * 33 + r] = v;
    }
    __syncthreads();

    constexpr GK gk = make_gk();
    const int cbase = wid * H_NOUT;

    float acc[H_NOUT];
#pragma unroll
    for (int i = 0; i < H_NOUT; i++) acc[i] = 0.0f;

#pragma unroll
    for (int j = 0; j < KSZ + H_NOUT - 1; j++) {      // 215 iters
        float v = s[(cbase + j) * 33 + lane];
#pragma unroll
        for (int i = 0; i < H_NOUT; i++) {
            int t = j - i;
            if (t >= 0 && t < KSZ) acc[i] += gk.v[t] * v;
        }
    }

    // transpose-stage outputs through shared for coalesced global stores
    __syncthreads();
#pragma unroll
    for (int i = 0; i < H_NOUT; i++) s[(cbase + i) * 33 + lane] = acc[i];
    __syncthreads();
    for (int idx = tid; idx < HT_C * 32; idx += 256) {
        int c = idx % HT_C;
        int r = idx / HT_C;
        g_tmp[(row0 + r) * Wd + c0 + c] = s[c * 33 + r];
    }
}

// ---------------- Pass 2: vertical blur (along H) ----------------------------
// Block: 256 threads = 32 cols (lane) x 8 warps; each warp 17 consecutive rows.
// Out tile: 136 rows x 32 cols; 544 = 4 * 136 exact. Shared: s[row][col32].
#define V_NOUT 17
#define VT_R   (8 * V_NOUT)          // 136
#define VS_R   (VT_R + 2 * PAD)      // 336 staged rows

__global__ void __launch_bounds__(256) vblur(float* __restrict__ y) {
    __shared__ float s[VS_R * 32];
    const int tid  = threadIdx.x;
    const int lane = tid & 31;       // col within 32-col group
    const int wid  = tid >> 5;
    const int frame = blockIdx.z;
    const int r0 = blockIdx.y * VT_R;
    const int c0 = blockIdx.x * 32;
    const float* xf = g_tmp + frame * (Hd * Wd);

    for (int idx = tid; idx < VS_R * 32; idx += 256) {
        int c = idx & 31;
        int r = idx >> 5;
        int gr = r0 - PAD + r;
        float v = 0.0f;
        if (gr >= 0 && gr < Hd) v = xf[gr * Wd + c0 + c];
        s[r * 32 + c] = v;
    }
    __syncthreads();

    constexpr GK gk = make_gk();
    const int rbase = wid * V_NOUT;

    float acc[V_NOUT];
#pragma unroll
    for (int i = 0; i < V_NOUT; i++) acc[i] = 0.0f;

#pragma unroll
    for (int j = 0; j < KSZ + V_NOUT - 1; j++) {      // 217 iters
        float v = s[(rbase + j) * 32 + lane];
#pragma unroll
        for (int i = 0; i < V_NOUT; i++) {
            int t = j - i;
            if (t >= 0 && t < KSZ) acc[i] += gk.v[t] * v;
        }
    }

    float* yf = y + frame * (Hd * Wd);
#pragma unroll
    for (int i = 0; i < V_NOUT; i++)
        yf[(r0 + rbase + i) * Wd + c0 + lane] = acc[i];   // coalesced
}

// ---------------- launch -----------------------------------------------------
extern "C" void kernel_launch(void* const* d_in, const int* in_sizes, int n_in,
                              void* d_out, int out_size) {
    const float* x = (const float*)d_in[0];
    float* out = (float*)d_out;

    hblur<<<dim3(Wd / HT_C, (Td * Hd) / 32), 256>>>(x);           // 8 x 1088
    vblur<<<dim3(Wd / 32, Hd / VT_R, Td), 256>>>(out);            // 30 x 4 x 64
}

// round 11
// speedup vs baseline: 1.4246x; 1.2415x over previous
#include <cuda_runtime.h>
#include <cuda_bf16.h>
#include <cstdint>

#define Wd 960
#define Hd 544
#define Td 64
#define PAD 100
#define KSZ 201

// ====================== constexpr Gaussian weights ===========================
__host__ __device__ constexpr double cexp(double x) {
    int n = (int)(x * 1.4426950408889634 - 0.5);   // x <= 0
    double r = x - (double)n * 0.69314718055994530941723212;
    double term = 1.0, p = 1.0;
    for (int k = 1; k <= 16; k++) { term *= r / (double)k; p += term; }
    double s = 1.0;
    for (int i = 0; i < -n; i++) s *= 0.5;
    return p * s;
}
struct GK { float v[KSZ]; };
__host__ __device__ constexpr GK make_gk() {
    GK g{};
    for (int i = 0; i < KSZ; i++) {
        double r = (double)(i - PAD);
        g.v[i] = (float)(cexp(-(r * r) / (2.0 * 25.0 * 25.0)) / 62.665706865775006);
    }
    return g;
}

// ====================== geometry ============================================
#define P1_N 120
#define P1_K 320            // 20 k16 chunks
#define P1_CH 20
#define PA1 328             // smem pitches (elements), 656B rows: conflict-free
#define PB1 328
#define P1_SMA 0
#define P1_SMB (128 * PA1 * 2)                 // 83968
#define P1_SMEM (P1_SMB + P1_N * PB1 * 2)      // 162688
#define TP1 136             // bf16 transpose buffer pitch

#define P2_N 136
#define P2_K 336            // 21 k16 chunks
#define P2_CH 21
#define P2_KS 384           // g_band2 row stride
#define PA2 344
#define PB2 344
#define P2_SMA 0
#define P2_SMB (128 * PA2 * 2)                 // 88064
#define P2_SMEM (P2_SMB + P2_N * PB2 * 2)      // 181632
#define TP2 132             // f32 transpose buffer pitch

__device__ __nv_bfloat16 g_band1[P1_N * P1_K];
__device__ __nv_bfloat16 g_band2[P2_N * P2_KS];
__device__ __nv_bfloat16 g_mid[(size_t)Td * Wd * Hd];   // [t][c][h]

// ====================== PTX helpers =========================================
__device__ __forceinline__ uint32_t smem_u32(const void* p) {
    uint32_t a;
    asm("{ .reg .u64 t; cvta.to.shared.u64 t, %1; cvt.u32.u64 %0, t; }"
        : "=r"(a) : "l"(p));
    return a;
}
__device__ __forceinline__ void ldsm4(uint32_t& r0, uint32_t& r1, uint32_t& r2,
                                      uint32_t& r3, uint32_t a) {
    asm volatile("ldmatrix.sync.aligned.m8n8.x4.shared.b16 {%0,%1,%2,%3}, [%4];"
        : "=r"(r0), "=r"(r1), "=r"(r2), "=r"(r3) : "r"(a));
}
__device__ __forceinline__ void ldsm2(uint32_t& r0, uint32_t& r1, uint32_t a) {
    asm volatile("ldmatrix.sync.aligned.m8n8.x2.shared.b16 {%0,%1}, [%2];"
        : "=r"(r0), "=r"(r1) : "r"(a));
}
__device__ __forceinline__ void mma16816(float* d, uint32_t a0, uint32_t a1,
                                         uint32_t a2, uint32_t a3,
                                         uint32_t b0, uint32_t b1) {
    asm volatile("mma.sync.aligned.m16n8k16.row.col.f32.bf16.bf16.f32 "
        "{%0,%1,%2,%3}, {%4,%5,%6,%7}, {%8,%9}, {%0,%1,%2,%3};"
        : "+f"(d[0]), "+f"(d[1]), "+f"(d[2]), "+f"(d[3])
        : "r"(a0), "r"(a1), "r"(a2), "r"(a3), "r"(b0), "r"(b1));
}

// ====================== init: band matrices =================================
__global__ void init_bands() {
    constexpr GK gk = make_gk();
    int i = blockIdx.x * 256 + threadIdx.x;
    if (i < P1_N * P1_K) {
        int n = i / P1_K, k = i % P1_K;
        int t = k - n;
        float v = (t >= 0 && t < KSZ) ? gk.v[t] : 0.0f;
        g_band1[i] = __float2bfloat16(v);
    }
    if (i < P2_N * P2_KS) {
        int n = i / P2_KS, k = i % P2_KS;
        int t = k - n;
        float v = (t >= 0 && t < KSZ && k < P2_K) ? gk.v[t] : 0.0f;
        g_band2[i] = __float2bfloat16(v);
    }
}

// ====================== Pass 1: blur along W, write [t][c][h] bf16 ===========
__global__ void __launch_bounds__(256) p1(const float* __restrict__ x) {
    extern __shared__ char smc[];
    uint32_t sb = smem_u32(smc);
    const int tid = threadIdx.x;
    const int wid = tid >> 5, lid = tid & 31;
    const int c0 = blockIdx.x * P1_N;
    const int row0 = blockIdx.y * 128;          // flat (t*Hd + h)

    // ---- stage A: 128 rows x 320 k, fp32 -> bf16 ----
    const int gc0 = c0 - PAD;                   // multiple of 4
    for (int i = tid; i < 128 * 40; i += 256) {
        int r = i / 40, j = i % 40;
        int gc = gc0 + j * 8;
        const float* src = x + (size_t)(row0 + r) * Wd + gc;
        float4 a = {0.f, 0.f, 0.f, 0.f}, b = {0.f, 0.f, 0.f, 0.f};
        if (gc >= 0 && gc + 3 < Wd)     a = *(const float4*)(src);
        if (gc + 4 >= 0 && gc + 7 < Wd) b = *(const float4*)(src + 4);
        __nv_bfloat162 q0 = __floats2bfloat162_rn(a.x, a.y);
        __nv_bfloat162 q1 = __floats2bfloat162_rn(a.z, a.w);
        __nv_bfloat162 q2 = __floats2bfloat162_rn(b.x, b.y);
        __nv_bfloat162 q3 = __floats2bfloat162_rn(b.z, b.w);
        uint4 w = { *(uint32_t*)&q0, *(uint32_t*)&q1, *(uint32_t*)&q2, *(uint32_t*)&q3 };
        *(uint4*)(smc + P1_SMA + ((size_t)r * PA1 + j * 8) * 2) = w;
    }
    // ---- stage B band [n][k] ----
    for (int i = tid; i < P1_N * 40; i += 256) {
        int r = i / 40, j = i % 40;
        uint4 w = *(const uint4*)(g_band1 + r * P1_K + j * 8);
        *(uint4*)(smc + P1_SMB + ((size_t)r * PB1 + j * 8) * 2) = w;
    }
    __syncthreads();

    // ---- mma mainloop: warp = one m16 strip ----
    const int mi = lid >> 3, lrow = lid & 7;
    const uint32_t aBase  = sb + P1_SMA +
        (((wid * 16) + ((mi & 1) << 3) + lrow) * PA1 + ((mi >> 1) << 3)) * 2;
    const uint32_t b4Base = sb + P1_SMB +
        ((((mi >> 1) << 3) + lrow) * PB1 + (mi & 1) * 8) * 2;
    const uint32_t b2Base = sb + P1_SMB +
        ((112 + (lid & 7)) * PB1 + ((lid >> 3) & 1) * 8) * 2;

    float acc[15][4];
#pragma unroll
    for (int nb = 0; nb < 15; nb++)
#pragma unroll
        for (int k = 0; k < 4; k++) acc[nb][k] = 0.f;

    for (int q = 0; q < P1_CH; q++) {
        uint32_t a0, a1, a2, a3;
        ldsm4(a0, a1, a2, a3, aBase + q * 32);
#pragma unroll
        for (int p = 0; p < 7; p++) {
            uint32_t b0, b1, b2, b3;
            ldsm4(b0, b1, b2, b3, b4Base + p * (16 * PB1 * 2) + q * 32);
            mma16816(acc[2 * p],     a0, a1, a2, a3, b0, b1);
            mma16816(acc[2 * p + 1], a0, a1, a2, a3, b2, b3);
        }
        uint32_t b0, b1;
        ldsm2(b0, b1, b2Base + q * 32);
        mma16816(acc[14], a0, a1, a2, a3, b0, b1);
    }
    __syncthreads();   // all ldmatrix reads done; A region reusable

    // ---- epilogue: acc -> bf16 transpose buffer tr[c][m] ----
    {
        const int g = lid >> 2, i2 = (lid & 3) * 2;
        const int mrow = wid * 16 + g;
        __nv_bfloat16* tr = (__nv_bfloat16*)smc;
#pragma unroll
        for (int nb = 0; nb < 15; nb++) {
            int c = nb * 8 + i2;
            tr[c * TP1 + mrow]           = __float2bfloat16(acc[nb][0]);
            tr[(c + 1) * TP1 + mrow]     = __float2bfloat16(acc[nb][1]);
            tr[c * TP1 + mrow + 8]       = __float2bfloat16(acc[nb][2]);
            tr[(c + 1) * TP1 + mrow + 8] = __float2bfloat16(acc[nb][3]);
        }
    }
    __syncthreads();

    // ---- coalesced store to g_mid[t][c][h] ----
    const int t0 = row0 / Hd, h0 = row0 % Hd;    // h0 multiple of 32
    const int rem = Hd - h0;
    const int len1 = (128 < rem) ? 128 : rem;    // multiple of 32
    const __nv_bfloat16* tr = (const __nv_bfloat16*)smc;
    for (int idx = tid; idx < P1_N * 32; idx += 256) {
        int c = idx >> 5, l = idx & 31, m = l * 4;
        uint2 w = *(const uint2*)(tr + c * TP1 + m);
        int t = t0, h = h0 + m;
        if (m >= len1) { t = t0 + 1; h = m - len1; }
        *(uint2*)(&g_mid[((size_t)t * Wd + (c0 + c)) * Hd + h]) = w;
    }
}

// ====================== Pass 2: blur along H, write out ======================
__global__ void __launch_bounds__(256) p2(float* __restrict__ out) {
    extern __shared__ char smc[];
    uint32_t sb = smem_u32(smc);
    const int tid = threadIdx.x;
    const int wid = tid >> 5, lid = tid & 31;
    const int h0o = blockIdx.x * P2_N;
    const int row0 = blockIdx.y * 128;           // flat (t*Wd + c)

    // ---- stage A: 128 rows x 336 k (bf16 copy from g_mid) ----
    const int gh0 = h0o - PAD;                   // multiple of 4
    for (int i = tid; i < 128 * 42; i += 256) {
        int r = i / 42, j = i % 42;
        int gh = gh0 + j * 8;
        const __nv_bfloat16* src = g_mid + (size_t)(row0 + r) * Hd + gh;
        uint2 w0 = {0u, 0u}, w1 = {0u, 0u};
        if (gh >= 0 && gh + 3 < Hd)     w0 = *(const uint2*)(src);
        if (gh + 4 >= 0 && gh + 7 < Hd) w1 = *(const uint2*)(src + 4);
        uint4 w = {w0.x, w0.y, w1.x, w1.y};
        *(uint4*)(smc + P2_SMA + ((size_t)r * PA2 + j * 8) * 2) = w;
    }
    // ---- stage B band [n][k] ----
    for (int i = tid; i < P2_N * 42; i += 256) {
        int r = i / 42, j = i % 42;
        uint4 w = *(const uint4*)(g_band2 + r * P2_KS + j * 8);
        *(uint4*)(smc + P2_SMB + ((size_t)r * PB2 + j * 8) * 2) = w;
    }
    __syncthreads();

    // ---- mma mainloop ----
    const int mi = lid >> 3, lrow = lid & 7;
    const uint32_t aBase  = sb + P2_SMA +
        (((wid * 16) + ((mi & 1) << 3) + lrow) * PA2 + ((mi >> 1) << 3)) * 2;
    const uint32_t b4Base = sb + P2_SMB +
        ((((mi >> 1) << 3) + lrow) * PB2 + (mi & 1) * 8) * 2;
    const uint32_t b2Base = sb + P2_SMB +
        ((128 + (lid & 7)) * PB2 + ((lid >> 3) & 1) * 8) * 2;

    float acc[17][4];
#pragma unroll
    for (int nb = 0; nb < 17; nb++)
#pragma unroll
        for (int k = 0; k < 4; k++) acc[nb][k] = 0.f;

    for (int q = 0; q < P2_CH; q++) {
        uint32_t a0, a1, a2, a3;
        ldsm4(a0, a1, a2, a3, aBase + q * 32);
#pragma unroll
        for (int p = 0; p < 8; p++) {
            uint32_t b0, b1, b2, b3;
            ldsm4(b0, b1, b2, b3, b4Base + p * (16 * PB2 * 2) + q * 32);
            mma16816(acc[2 * p],     a0, a1, a2, a3, b0, b1);
            mma16816(acc[2 * p + 1], a0, a1, a2, a3, b2, b3);
        }
        uint32_t b0, b1;
        ldsm2(b0, b1, b2Base + q * 32);
        mma16816(acc[16], a0, a1, a2, a3, b0, b1);
    }
    __syncthreads();

    // ---- epilogue: acc -> f32 transpose buffer tr[n][m] ----
    {
        const int g = lid >> 2, i2 = (lid & 3) * 2;
        const int mrow = wid * 16 + g;
        float* tr = (float*)smc;
#pragma unroll
        for (int nb = 0; nb < 17; nb++) {
            int c = nb * 8 + i2;
            tr[c * TP2 + mrow]           = acc[nb][0];
            tr[(c + 1) * TP2 + mrow]     = acc[nb][1];
            tr[c * TP2 + mrow + 8]       = acc[nb][2];
            tr[(c + 1) * TP2 + mrow + 8] = acc[nb][3];
        }
    }
    __syncthreads();

    // ---- coalesced store to out[t][h][w] ----
    const int t0 = row0 / Wd, cst = row0 % Wd;   // cst multiple of 64
    const int rem = Wd - cst;
    const int len1 = (128 < rem) ? 128 : rem;    // multiple of 64
    const float* tr = (const float*)smc;
    for (int idx = tid; idx < P2_N * 32; idx += 256) {
        int n = idx >> 5, l = idx & 31, m = l * 4;
        float4 w = *(const float4*)(tr + n * TP2 + m);
        int t = t0, c = cst + m;
        if (m >= len1) { t = t0 + 1; c = m - len1; }
        *(float4*)(&out[((size_t)t * Hd + (h0o + n)) * Wd + c]) = w;
    }
}

// ====================== launch ==============================================
extern "C" void kernel_launch(void* const* d_in, const int* in_sizes, int n_in,
                              void* d_out, int out_size) {
    const float* x = (const float*)d_in[0];
    float* out = (float*)d_out;

    cudaFuncSetAttribute(p1, cudaFuncAttributeMaxDynamicSharedMemorySize, P1_SMEM);
    cudaFuncSetAttribute(p2, cudaFuncAttributeMaxDynamicSharedMemorySize, P2_SMEM);

    init_bands<<<(P2_N * P2_KS + 255) / 256, 256>>>();
    p1<<<dim3(Wd / P1_N, (Td * Hd) / 128), 256, P1_SMEM>>>(x);
    p2<<<dim3(Hd / P2_N, (Td * Wd) / 128), 256, P2_SMEM>>>(out);
}

// round 12
// speedup vs baseline: 1.8018x; 1.2648x over previous
#include <cuda_runtime.h>
#include <cuda_bf16.h>
#include <cstdint>

#define Wd 960
#define Hd 544
#define Td 64
#define PAD 100
#define KSZ 201

// ====================== constexpr Gaussian weights ===========================
__host__ __device__ constexpr double cexp(double x) {
    int n = (int)(x * 1.4426950408889634 - 0.5);   // x <= 0
    double r = x - (double)n * 0.69314718055994530941723212;
    double term = 1.0, p = 1.0;
    for (int k = 1; k <= 16; k++) { term *= r / (double)k; p += term; }
    double s = 1.0;
    for (int i = 0; i < -n; i++) s *= 0.5;
    return p * s;
}
struct GK { float v[KSZ]; };
__host__ __device__ constexpr GK make_gk() {
    GK g{};
    for (int i = 0; i < KSZ; i++) {
        double r = (double)(i - PAD);
        g.v[i] = (float)(cexp(-(r * r) / (2.0 * 25.0 * 25.0)) / 62.665706865775006);
    }
    return g;
}

// ====================== geometry ============================================
#define P1_N 120
#define P1_K 320            // 20 k16 chunks
#define P1_CH 20
#define PA1 328             // smem pitches (elements); 656B rows: conflict-free
#define PB1 328
#define P1_SMA 0
#define P1_SMB (128 * PA1 * 2)
#define P1_SMEM (P1_SMB + P1_N * PB1 * 2)
#define TP1 136             // bf16 transpose buffer pitch

#define P2_N 136
#define P2_K 336            // 21 k16 chunks
#define P2_CH 21
#define P2_KS 384           // g_band2 row stride
#define PA2 344
#define PB2 344
#define P2_SMA 0
#define P2_SMB (128 * PA2 * 2)
#define P2_SMEM (P2_SMB + P2_N * PB2 * 2)
#define TP2 132             // f32 transpose buffer pitch

#define NT 512              // threads per CTA (16 warps)

__device__ __nv_bfloat16 g_band1[P1_N * P1_K];
__device__ __nv_bfloat16 g_band2[P2_N * P2_KS];
__device__ __nv_bfloat16 g_mid[(size_t)Td * Wd * Hd];   // [t][c][h]

// ====================== PTX helpers =========================================
__device__ __forceinline__ uint32_t smem_u32(const void* p) {
    uint32_t a;
    asm("{ .reg .u64 t; cvta.to.shared.u64 t, %1; cvt.u32.u64 %0, t; }"
        : "=r"(a) : "l"(p));
    return a;
}
__device__ __forceinline__ void ldsm4(uint32_t& r0, uint32_t& r1, uint32_t& r2,
                                      uint32_t& r3, uint32_t a) {
    asm volatile("ldmatrix.sync.aligned.m8n8.x4.shared.b16 {%0,%1,%2,%3}, [%4];"
        : "=r"(r0), "=r"(r1), "=r"(r2), "=r"(r3) : "r"(a));
}
__device__ __forceinline__ void ldsm2(uint32_t& r0, uint32_t& r1, uint32_t a) {
    asm volatile("ldmatrix.sync.aligned.m8n8.x2.shared.b16 {%0,%1}, [%2];"
        : "=r"(r0), "=r"(r1) : "r"(a));
}
__device__ __forceinline__ void mma16816(float* d, uint32_t a0, uint32_t a1,
                                         uint32_t a2, uint32_t a3,
                                         uint32_t b0, uint32_t b1) {
    asm volatile("mma.sync.aligned.m16n8k16.row.col.f32.bf16.bf16.f32 "
        "{%0,%1,%2,%3}, {%4,%5,%6,%7}, {%8,%9}, {%0,%1,%2,%3};"
        : "+f"(d[0]), "+f"(d[1]), "+f"(d[2]), "+f"(d[3])
        : "r"(a0), "r"(a1), "r"(a2), "r"(a3), "r"(b0), "r"(b1));
}

// ====================== banded mainloop (band-skip, fully unrolled) =========
// Block p (8 out-cols at n=8p) needs k in [8p, 8p+208); chunk q (k16) hits
// block p iff p in [2q-25, 2q+1]. All bounds constant-fold under full unroll.
template<int B0, int NB, int CH, int PBp>
__device__ __forceinline__ void band_mainloop(uint32_t aBase, uint32_t b4Base,
                                              uint32_t b2Base, float (*acc)[4]) {
#pragma unroll
    for (int q = 0; q < CH; q++) {
        int lo = 2 * q - 25; if (lo < B0) lo = B0;
        int hi = 2 * q + 1;  if (hi > B0 + NB - 1) hi = B0 + NB - 1;
        if (lo > hi) continue;
        uint32_t a0, a1, a2, a3;
        ldsm4(a0, a1, a2, a3, aBase + q * 32);
#pragma unroll
        for (int u = B0 / 2; u < (B0 + (NB & ~1)) / 2; u++) {
            bool n0 = (2 * u >= lo) && (2 * u <= hi);
            bool n1 = (2 * u + 1 >= lo) && (2 * u + 1 <= hi);
            if (n0 || n1) {
                uint32_t b0, b1, b2, b3;
                ldsm4(b0, b1, b2, b3, b4Base + u * (16 * PBp * 2) + q * 32);
                if (n0) mma16816(acc[2 * u - B0],     a0, a1, a2, a3, b0, b1);
                if (n1) mma16816(acc[2 * u + 1 - B0], a0, a1, a2, a3, b2, b3);
            }
        }
        if (NB & 1) {
            int t = B0 + NB - 1;
            if (t >= lo && t <= hi) {
                uint32_t b0, b1;
                ldsm2(b0, b1, b2Base + q * 32);
                mma16816(acc[NB - 1], a0, a1, a2, a3, b0, b1);
            }
        }
    }
}

template<int B0, int NB, int TP>
__device__ __forceinline__ void epi_bf16(char* smc, int mrow, int i2,
                                         float (*acc)[4]) {
    __nv_bfloat16* tr = (__nv_bfloat16*)smc;
#pragma unroll
    for (int nb = 0; nb < NB; nb++) {
        int c = (B0 + nb) * 8 + i2;
        tr[c * TP + mrow]           = __float2bfloat16(acc[nb][0]);
        tr[(c + 1) * TP + mrow]     = __float2bfloat16(acc[nb][1]);
        tr[c * TP + mrow + 8]       = __float2bfloat16(acc[nb][2]);
        tr[(c + 1) * TP + mrow + 8] = __float2bfloat16(acc[nb][3]);
    }
}
template<int B0, int NB, int TP>
__device__ __forceinline__ void epi_f32(char* smc, int mrow, int i2,
                                        float (*acc)[4]) {
    float* tr = (float*)smc;
#pragma unroll
    for (int nb = 0; nb < NB; nb++) {
        int c = (B0 + nb) * 8 + i2;
        tr[c * TP + mrow]           = acc[nb][0];
        tr[(c + 1) * TP + mrow]     = acc[nb][1];
        tr[c * TP + mrow + 8]       = acc[nb][2];
        tr[(c + 1) * TP + mrow + 8] = acc[nb][3];
    }
}

// ====================== init: band matrices =================================
__global__ void init_bands() {
    constexpr GK gk = make_gk();
    int i = blockIdx.x * 256 + threadIdx.x;
    if (i < P1_N * P1_K) {
        int n = i / P1_K, k = i % P1_K;
        int t = k - n;
        float v = (t >= 0 && t < KSZ) ? gk.v[t] : 0.0f;
        g_band1[i] = __float2bfloat16(v);
    }
    if (i < P2_N * P2_KS) {
        int n = i / P2_KS, k = i % P2_KS;
        int t = k - n;
        float v = (t >= 0 && t < KSZ && k < P2_K) ? gk.v[t] : 0.0f;
        g_band2[i] = __float2bfloat16(v);
    }
}

// ====================== Pass 1: blur along W, write [t][c][h] bf16 ===========
__global__ void __launch_bounds__(NT) p1(const float* __restrict__ x) {
    extern __shared__ char smc[];
    uint32_t sb = smem_u32(smc);
    const int tid = threadIdx.x;
    const int wid = tid >> 5, lid = tid & 31;
    const int wm = wid & 7, h = wid >> 3;     // m-strip, n-half
    const int c0 = blockIdx.x * P1_N;
    const int row0 = blockIdx.y * 128;        // flat (t*Hd + h)

    // ---- stage A: 128 rows x 320 k, fp32 -> bf16 ----
    const int gc0 = c0 - PAD;                 // multiple of 4
    for (int i = tid; i < 128 * 40; i += NT) {
        int r = i / 40, j = i % 40;
        int gc = gc0 + j * 8;
        const float* src = x + (size_t)(row0 + r) * Wd + gc;
        float4 a = {0.f, 0.f, 0.f, 0.f}, b = {0.f, 0.f, 0.f, 0.f};
        if (gc >= 0 && gc + 3 < Wd)     a = *(const float4*)(src);
        if (gc + 4 >= 0 && gc + 7 < Wd) b = *(const float4*)(src + 4);
        __nv_bfloat162 q0 = __floats2bfloat162_rn(a.x, a.y);
        __nv_bfloat162 q1 = __floats2bfloat162_rn(a.z, a.w);
        __nv_bfloat162 q2 = __floats2bfloat162_rn(b.x, b.y);
        __nv_bfloat162 q3 = __floats2bfloat162_rn(b.z, b.w);
        uint4 w = { *(uint32_t*)&q0, *(uint32_t*)&q1, *(uint32_t*)&q2, *(uint32_t*)&q3 };
        *(uint4*)(smc + P1_SMA + ((size_t)r * PA1 + j * 8) * 2) = w;
    }
    // ---- stage B band [n][k] ----
    for (int i = tid; i < P1_N * 40; i += NT) {
        int r = i / 40, j = i % 40;
        uint4 w = *(const uint4*)(g_band1 + r * P1_K + j * 8);
        *(uint4*)(smc + P1_SMB + ((size_t)r * PB1 + j * 8) * 2) = w;
    }
    __syncthreads();

    // ---- mma mainloop: warp = (m16 strip, n-half) ----
    const int mi = lid >> 3, lrow = lid & 7;
    const uint32_t aBase  = sb + P1_SMA +
        (((wm * 16) + ((mi & 1) << 3) + lrow) * PA1 + ((mi >> 1) << 3)) * 2;
    const uint32_t b4Base = sb + P1_SMB +
        ((((mi >> 1) << 3) + lrow) * PB1 + (mi & 1) * 8) * 2;
    const uint32_t b2Base = sb + P1_SMB +
        ((112 + (lid & 7)) * PB1 + ((lid >> 3) & 1) * 8) * 2;

    float acc[9][4];
#pragma unroll
    for (int nb = 0; nb < 9; nb++)
#pragma unroll
        for (int k = 0; k < 4; k++) acc[nb][k] = 0.f;

    if (h == 0) band_mainloop<0, 8, P1_CH, PB1>(aBase, b4Base, b2Base, acc);
    else        band_mainloop<8, 7, P1_CH, PB1>(aBase, b4Base, b2Base, acc);
    __syncthreads();   // ldmatrix reads done; A region reusable

    // ---- epilogue: acc -> bf16 transpose buffer tr[c][m] ----
    {
        const int g = lid >> 2, i2 = (lid & 3) * 2;
        const int mrow = wm * 16 + g;
        if (h == 0) epi_bf16<0, 8, TP1>(smc, mrow, i2, acc);
        else        epi_bf16<8, 7, TP1>(smc, mrow, i2, acc);
    }
    __syncthreads();

    // ---- coalesced store to g_mid[t][c][h] ----
    const int t0 = row0 / Hd, h0 = row0 % Hd;    // h0 multiple of 32
    const int rem = Hd - h0;
    const int len1 = (128 < rem) ? 128 : rem;    // multiple of 32
    const __nv_bfloat16* tr = (const __nv_bfloat16*)smc;
    for (int idx = tid; idx < P1_N * 32; idx += NT) {
        int c = idx >> 5, l = idx & 31, m = l * 4;
        uint2 w = *(const uint2*)(tr + c * TP1 + m);
        int t = t0, hh = h0 + m;
        if (m >= len1) { t = t0 + 1; hh = m - len1; }
        *(uint2*)(&g_mid[((size_t)t * Wd + (c0 + c)) * Hd + hh]) = w;
    }
}

// ====================== Pass 2: blur along H, write out ======================
__global__ void __launch_bounds__(NT) p2(float* __restrict__ out) {
    extern __shared__ char smc[];
    uint32_t sb = smem_u32(smc);
    const int tid = threadIdx.x;
    const int wid = tid >> 5, lid = tid & 31;
    const int wm = wid & 7, h = wid >> 3;
    const int h0o = blockIdx.x * P2_N;
    const int row0 = blockIdx.y * 128;           // flat (t*Wd + c)

    // ---- stage A: 128 rows x 336 k (bf16 copy from g_mid) ----
    const int gh0 = h0o - PAD;                   // multiple of 4
    for (int i = tid; i < 128 * 42; i += NT) {
        int r = i / 42, j = i % 42;
        int gh = gh0 + j * 8;
        const __nv_bfloat16* src = g_mid + (size_t)(row0 + r) * Hd + gh;
        uint2 w0 = {0u, 0u}, w1 = {0u, 0u};
        if (gh >= 0 && gh + 3 < Hd)     w0 = *(const uint2*)(src);
        if (gh + 4 >= 0 && gh + 7 < Hd) w1 = *(const uint2*)(src + 4);
        uint4 w = {w0.x, w0.y, w1.x, w1.y};
        *(uint4*)(smc + P2_SMA + ((size_t)r * PA2 + j * 8) * 2) = w;
    }
    // ---- stage B band [n][k] ----
    for (int i = tid; i < P2_N * 42; i += NT) {
        int r = i / 42, j = i % 42;
        uint4 w = *(const uint4*)(g_band2 + r * P2_KS + j * 8);
        *(uint4*)(smc + P2_SMB + ((size_t)r * PB2 + j * 8) * 2) = w;
    }
    __syncthreads();

    // ---- mma mainloop ----
    const int mi = lid >> 3, lrow = lid & 7;
    const uint32_t aBase  = sb + P2_SMA +
        (((wm * 16) + ((mi & 1) << 3) + lrow) * PA2 + ((mi >> 1) << 3)) * 2;
    const uint32_t b4Base = sb + P2_SMB +
        ((((mi >> 1) << 3) + lrow) * PB2 + (mi & 1) * 8) * 2;
    const uint32_t b2Base = sb + P2_SMB +
        ((128 + (lid & 7)) * PB2 + ((lid >> 3) & 1) * 8) * 2;

    float acc[9][4];
#pragma unroll
    for (int nb = 0; nb < 9; nb++)
#pragma unroll
        for (int k = 0; k < 4; k++) acc[nb][k] = 0.f;

    if (h == 0) band_mainloop<0, 8, P2_CH, PB2>(aBase, b4Base, b2Base, acc);
    else        band_mainloop<8, 9, P2_CH, PB2>(aBase, b4Base, b2Base, acc);
    __syncthreads();

    // ---- epilogue: acc -> f32 transpose buffer tr[n][m] ----
    {
        const int g = lid >> 2, i2 = (lid & 3) * 2;
        const int mrow = wm * 16 + g;
        if (h == 0) epi_f32<0, 8, TP2>(smc, mrow, i2, acc);
        else        epi_f32<8, 9, TP2>(smc, mrow, i2, acc);
    }
    __syncthreads();

    // ---- coalesced store to out[t][h][w] ----
    const int t0 = row0 / Wd, cst = row0 % Wd;   // cst multiple of 64
    const int rem = Wd - cst;
    const int len1 = (128 < rem) ? 128 : rem;    // multiple of 64
    const float* tr = (const float*)smc;
    for (int idx = tid; idx < P2_N * 32; idx += NT) {
        int n = idx >> 5, l = idx & 31, m = l * 4;
        float4 w = *(const float4*)(tr + n * TP2 + m);
        int t = t0, c = cst + m;
        if (m >= len1) { t = t0 + 1; c = m - len1; }
        *(float4*)(&out[((size_t)t * Hd + (h0o + n)) * Wd + c]) = w;
    }
}

// ====================== launch ==============================================
extern "C" void kernel_launch(void* const* d_in, const int* in_sizes, int n_in,
                              void* d_out, int out_size) {
    const float* x = (const float*)d_in[0];
    float* out = (float*)d_out;

    cudaFuncSetAttribute(p1, cudaFuncAttributeMaxDynamicSharedMemorySize, P1_SMEM);
    cudaFuncSetAttribute(p2, cudaFuncAttributeMaxDynamicSharedMemorySize, P2_SMEM);

    init_bands<<<(P2_N * P2_KS + 255) / 256, 256>>>();
    p1<<<dim3(Wd / P1_N, (Td * Hd) / 128), NT, P1_SMEM>>>(x);
    p2<<<dim3(Hd / P2_N, (Td * Wd) / 128), NT, P2_SMEM>>>(out);
}